// round 4
// baseline (speedup 1.0000x reference)
#include <cuda_runtime.h>

// Bandpass (HP1 x LP1 collapsed to one biquad), B=128 rows, T=262144.
// Shared-memory staged: each block owns an 8192-sample span of one row.
//   fill:    coalesced gmem -> smem (span + 132 floats of history, zero-padded)
//   compute: 128 threads x 64-sample chunks, 128-sample smem warm-up each
//   drain:   smem -> gmem coalesced
// Swizzle (16B-granular XOR) makes the stride-64 compute accesses conflict-free.

static constexpr int BLOCK = 128;
static constexpr int CH    = 64;                  // owned samples / thread
static constexpr int WARM  = 128;                 // warm-up (pole^128 ~ 3e-6)
static constexpr int SPAN  = BLOCK * CH;          // 8192 samples / block
static constexpr int PRE   = WARM + 4;            // history floats staged before span
static constexpr int IN_WORDS  = ((SPAN + PRE + 63) / 64) * 64;   // 8384
static constexpr int OUT_WORDS = SPAN;                            // 8192
static constexpr int SMEM_BYTES = (IN_WORDS + OUT_WORDS) * 4;     // 66304

// 16B-granular bank swizzle: keeps float4 groups contiguous, spreads banks.
#define SW(w) ((w) ^ ((((w) >> 6) & 7) << 2))

__global__ __launch_bounds__(BLOCK)
void bandpass_kernel(const float* __restrict__ x,
                     const float* __restrict__ p_cf,
                     const float* __restrict__ p_bw,
                     const float* __restrict__ p_gain,
                     const int*   __restrict__ p_sr,
                     float* __restrict__ out,
                     int T, int blocks_per_row)
{
    extern __shared__ float smem[];
    float* __restrict__ s_in  = smem;              // IN_WORDS floats
    float* __restrict__ s_out = smem + IN_WORDS;   // OUT_WORDS floats

    const int tid  = threadIdx.x;
    const int row  = blockIdx.x / blocks_per_row;
    const int sblk = blockIdx.x - row * blocks_per_row;
    const int S0   = sblk * SPAN;

    const float* __restrict__ xr   = x   + (size_t)row * T;
    float* __restrict__       orow = out + (size_t)row * T;

    // ---- biquad coefficients (HP1 x LP1 product, scipy butter(1,.) bilinear) ----
    const float cf   = *p_cf;
    const float bw   = *p_bw;
    const float gain = *p_gain;
    const float nyq  = 0.5f * (float)(*p_sr);
    const float PI_  = 3.14159265358979323846f;

    const float Kh  = tanf(PI_ * ((cf - 0.5f * bw) / nyq) * 0.5f);
    const float ah1 = (Kh - 1.0f) / (Kh + 1.0f);
    const float bh0 = 1.0f / (Kh + 1.0f);
    const float Kl  = tanf(PI_ * ((cf + 0.5f * bw) / nyq) * 0.5f);
    const float al1 = (Kl - 1.0f) / (Kl + 1.0f);
    const float bl0 = Kl / (Kl + 1.0f);

    const float na1 = -(ah1 + al1);      // y[t] = na1*y[t-1] + na2*y[t-2] + gg*(x[t]-x[t-2])
    const float na2 = -(ah1 * al1);
    const float gg  = bh0 * bl0 * gain;  // gain folded into the numerator

    // ---- fill: coalesced load of [S0-PRE, S0+SPAN) (row-local, zeros before 0) ----
    {
        const int total4 = (SPAN + PRE) / 4;            // 2081
        for (int idx = tid; idx < total4; idx += BLOCK) {
            const int e = S0 - PRE + 4 * idx;           // row-local element
            float4 v;
            if (e >= 0) v = *reinterpret_cast<const float4*>(xr + e);
            else        v = make_float4(0.f, 0.f, 0.f, 0.f);
            const int w = 4 * idx;
            *reinterpret_cast<float4*>(s_in + SW(w)) = v;
        }
    }
    __syncthreads();

    // ---- compute: thread tid owns logical samples [PRE + tid*CH, PRE + (tid+1)*CH) ----
    {
        const int base = 4 + tid * CH;                  // warm-up start (logical)
        float x_1 = s_in[SW(base - 1)];
        float x_2 = s_in[SW(base - 2)];
        float y_1 = 0.0f, y_2 = 0.0f;

        #define BQ_STEP(XC, YO)                               \
            {                                                 \
                float d_  = gg * ((XC) - x_2);                \
                float t0_ = fmaf(na2, y_2, d_);               \
                float yn_ = fmaf(na1, y_1, t0_);              \
                x_2 = x_1; x_1 = (XC);                        \
                y_2 = y_1; y_1 = yn_;                         \
                (YO) = yn_;                                   \
            }

        // warm-up: no stores
        #pragma unroll 4
        for (int j = 0; j < WARM; j += 4) {
            float4 v = *reinterpret_cast<const float4*>(s_in + SW(base + j));
            float d;
            BQ_STEP(v.x, d); BQ_STEP(v.y, d); BQ_STEP(v.z, d); BQ_STEP(v.w, d);
            (void)d;
        }
        // owned samples -> out smem
        #pragma unroll 4
        for (int j = 0; j < CH; j += 4) {
            float4 v = *reinterpret_cast<const float4*>(s_in + SW(base + WARM + j));
            float4 o;
            BQ_STEP(v.x, o.x); BQ_STEP(v.y, o.y); BQ_STEP(v.z, o.z); BQ_STEP(v.w, o.w);
            *reinterpret_cast<float4*>(s_out + SW(tid * CH + j)) = o;
        }
        #undef BQ_STEP
    }
    __syncthreads();

    // ---- drain: coalesced smem -> gmem ----
    {
        const int iters = SPAN / 4 / BLOCK;             // 16
        #pragma unroll
        for (int m = 0; m < iters; m++) {
            const int w = 4 * (m * BLOCK + tid);
            float4 v = *reinterpret_cast<const float4*>(s_out + SW(w));
            *reinterpret_cast<float4*>(orow + S0 + w) = v;
        }
    }
}

extern "C" void kernel_launch(void* const* d_in, const int* in_sizes, int n_in,
                              void* d_out, int out_size)
{
    const float* x    = (const float*)d_in[0];
    const float* cf   = (const float*)d_in[1];
    const float* bw   = (const float*)d_in[2];
    const float* gain = (const float*)d_in[3];
    const int*   sr   = (const int*)  d_in[4];
    float*       out  = (float*)d_out;

    const int B = 128;
    const int T = in_sizes[0] / B;                 // 262144
    const int blocks_per_row = T / SPAN;           // 32
    const int grid = B * blocks_per_row;           // 4096

    cudaFuncSetAttribute(bandpass_kernel,
                         cudaFuncAttributeMaxDynamicSharedMemorySize, SMEM_BYTES);
    bandpass_kernel<<<grid, BLOCK, SMEM_BYTES>>>(x, cf, bw, gain, sr, out,
                                                 T, blocks_per_row);
}

// round 5
// speedup vs baseline: 1.8677x; 1.8677x over previous
#include <cuda_runtime.h>

// Bandpass (HP1 x LP1 collapsed to one biquad), B=128 rows, T=262144.
// Shared-memory staged: each block owns a 4096-sample span of one row.
//   fill:    coalesced gmem -> smem (span + 100 floats of history, zero-padded)
//   compute: 128 threads x 32-sample chunks, 96-sample smem warm-up each
//   drain:   smem -> gmem coalesced
// 33.3KB smem/block -> 6 blocks/SM so phases overlap across resident blocks.

static constexpr int BLOCK = 128;
static constexpr int CH    = 32;                  // owned samples / thread
static constexpr int WARM  = 96;                  // pole^96 ~ 7.6e-5 residual
static constexpr int SPAN  = BLOCK * CH;          // 4096 samples / block
static constexpr int PRE   = WARM + 4;            // history staged before span
static constexpr int IN_WORDS  = ((SPAN + PRE + 63) / 64) * 64;   // 4224
static constexpr int OUT_WORDS = SPAN;                            // 4096
static constexpr int SMEM_BYTES = (IN_WORDS + OUT_WORDS) * 4;     // 33280

// 16B-granular bank swizzle tuned for stride-32 compute accesses:
// every 8-lane LDS.128 phase hits 32 distinct banks; sequential fill/drain
// accesses get a uniform XOR within each 32-word group (still conflict-free).
#define SW(w) ((w) ^ ((((w) >> 5) & 7) << 2))

__global__ __launch_bounds__(BLOCK)
void bandpass_kernel(const float* __restrict__ x,
                     const float* __restrict__ p_cf,
                     const float* __restrict__ p_bw,
                     const float* __restrict__ p_gain,
                     const int*   __restrict__ p_sr,
                     float* __restrict__ out,
                     int T, int blocks_per_row)
{
    extern __shared__ float smem[];
    float* __restrict__ s_in  = smem;              // IN_WORDS floats
    float* __restrict__ s_out = smem + IN_WORDS;   // OUT_WORDS floats

    const int tid  = threadIdx.x;
    const int row  = blockIdx.x / blocks_per_row;
    const int sblk = blockIdx.x - row * blocks_per_row;
    const int S0   = sblk * SPAN;

    const float* __restrict__ xr   = x   + (size_t)row * T;
    float* __restrict__       orow = out + (size_t)row * T;

    // ---- biquad coefficients (HP1 x LP1 product, scipy butter(1,.) bilinear) ----
    const float cf   = *p_cf;
    const float bw   = *p_bw;
    const float gain = *p_gain;
    const float nyq  = 0.5f * (float)(*p_sr);
    const float PI_  = 3.14159265358979323846f;

    const float Kh  = tanf(PI_ * ((cf - 0.5f * bw) / nyq) * 0.5f);
    const float ah1 = (Kh - 1.0f) / (Kh + 1.0f);
    const float bh0 = 1.0f / (Kh + 1.0f);
    const float Kl  = tanf(PI_ * ((cf + 0.5f * bw) / nyq) * 0.5f);
    const float al1 = (Kl - 1.0f) / (Kl + 1.0f);
    const float bl0 = Kl / (Kl + 1.0f);

    const float na1 = -(ah1 + al1);      // y[t] = na1*y[t-1] + na2*y[t-2] + gg*(x[t]-x[t-2])
    const float na2 = -(ah1 * al1);
    const float gg  = bh0 * bl0 * gain;  // gain (and DF gains) folded in

    // ---- fill: coalesced load of [S0-PRE, S0+SPAN) (row-local, zeros before 0) ----
    {
        const int total4 = (SPAN + PRE) / 4;            // 1049
        #pragma unroll
        for (int m = 0; m < (total4 + BLOCK - 1) / BLOCK; m++) {
            const int idx = m * BLOCK + tid;
            if (idx < total4) {
                const int e = S0 - PRE + 4 * idx;       // row-local element
                float4 v;
                if (e >= 0) v = *reinterpret_cast<const float4*>(xr + e);
                else        v = make_float4(0.f, 0.f, 0.f, 0.f);
                const int w = 4 * idx;
                *reinterpret_cast<float4*>(s_in + SW(w)) = v;
            }
        }
    }
    __syncthreads();

    // ---- compute: thread tid owns row samples [S0+tid*CH, S0+(tid+1)*CH) ----
    {
        const int base = 4 + tid * CH;                  // warm-up start (smem word)
        float x_1 = s_in[SW(base - 1)];
        float x_2 = s_in[SW(base - 2)];
        float y_1 = 0.0f, y_2 = 0.0f;

        #define BQ_STEP(XC, YO)                               \
            {                                                 \
                float d_  = gg * ((XC) - x_2);                \
                float t0_ = fmaf(na2, y_2, d_);               \
                float yn_ = fmaf(na1, y_1, t0_);              \
                x_2 = x_1; x_1 = (XC);                        \
                y_2 = y_1; y_1 = yn_;                         \
                (YO) = yn_;                                   \
            }

        // warm-up: no stores
        #pragma unroll 4
        for (int j = 0; j < WARM; j += 4) {
            float4 v = *reinterpret_cast<const float4*>(s_in + SW(base + j));
            float d;
            BQ_STEP(v.x, d); BQ_STEP(v.y, d); BQ_STEP(v.z, d); BQ_STEP(v.w, d);
            (void)d;
        }
        // owned samples -> out smem
        #pragma unroll 4
        for (int j = 0; j < CH; j += 4) {
            float4 v = *reinterpret_cast<const float4*>(s_in + SW(base + WARM + j));
            float4 o;
            BQ_STEP(v.x, o.x); BQ_STEP(v.y, o.y); BQ_STEP(v.z, o.z); BQ_STEP(v.w, o.w);
            *reinterpret_cast<float4*>(s_out + SW(tid * CH + j)) = o;
        }
        #undef BQ_STEP
    }
    __syncthreads();

    // ---- drain: coalesced smem -> gmem ----
    {
        const int iters = SPAN / 4 / BLOCK;             // 8
        #pragma unroll
        for (int m = 0; m < iters; m++) {
            const int w = 4 * (m * BLOCK + tid);
            float4 v = *reinterpret_cast<const float4*>(s_out + SW(w));
            *reinterpret_cast<float4*>(orow + S0 + w) = v;
        }
    }
}

extern "C" void kernel_launch(void* const* d_in, const int* in_sizes, int n_in,
                              void* d_out, int out_size)
{
    const float* x    = (const float*)d_in[0];
    const float* cf   = (const float*)d_in[1];
    const float* bw   = (const float*)d_in[2];
    const float* gain = (const float*)d_in[3];
    const int*   sr   = (const int*)  d_in[4];
    float*       out  = (float*)d_out;

    const int B = 128;
    const int T = in_sizes[0] / B;                 // 262144
    const int blocks_per_row = T / SPAN;           // 64
    const int grid = B * blocks_per_row;           // 8192

    cudaFuncSetAttribute(bandpass_kernel,
                         cudaFuncAttributeMaxDynamicSharedMemorySize, SMEM_BYTES);
    bandpass_kernel<<<grid, BLOCK, SMEM_BYTES>>>(x, cf, bw, gain, sr, out,
                                                 T, blocks_per_row);
}

// round 7
// speedup vs baseline: 2.4712x; 1.3231x over previous
#include <cuda_runtime.h>

// Bandpass biquad (HP1 x LP1), B=128 rows, T=262144. Exact block-level scan:
//   fill:   coalesced gmem -> smem span [S0-260, S0+4096)
//   pass1:  each thread filters its 32 samples from ZERO y-state (exact x hist),
//           keeping outputs p[0..31] in registers and final state f=(y31,y30)
//   hist:   warp 0 filters 8x32 history chunks; composes block-in state s_blk
//   scan:   within-warp inclusive affine scan (uniform level matrices, valid
//           under the lane>=d guard) + per-thread V=A^(32*lane) built from the
//           level matrices + serial 4-entry warp-aggregate composition.
//           delta_tid = V*W_warp + Q_lane (exclusive within-warp offset).
//   pass2:  add homogeneous correction seeded by delta; write into reused s_in;
//           coalesced drain.

static constexpr int BLOCK = 128;
static constexpr int CH    = 32;                  // owned samples / thread
static constexpr int NHIST = 8;                   // 8*32 = 256-sample history
static constexpr int SPAN  = BLOCK * CH;          // 4096
static constexpr int PRE   = NHIST * CH + 4;      // 260
static constexpr int IN_WORDS = SPAN + PRE;       // 4356
static constexpr int SMEM_BYTES = IN_WORDS * 4 + 8 * sizeof(float2);

// 16B-granular bank swizzle for stride-32 accesses (pure permutation).
#define SW(w) ((w) ^ ((((w) >> 5) & 7) << 2))

struct M2 { float a, b, c, d; };                  // [[a,b],[c,d]]
__device__ __forceinline__ M2 msq(M2 m) {         // m*m
    M2 r;
    r.a = fmaf(m.a, m.a, m.b * m.c);
    r.b = fmaf(m.a, m.b, m.b * m.d);
    r.c = fmaf(m.c, m.a, m.d * m.c);
    r.d = fmaf(m.c, m.b, m.d * m.d);
    return r;
}
__device__ __forceinline__ M2 mmul(M2 p, M2 q) {  // p*q
    M2 r;
    r.a = fmaf(p.a, q.a, p.b * q.c);
    r.b = fmaf(p.a, q.b, p.b * q.d);
    r.c = fmaf(p.c, q.a, p.d * q.c);
    r.d = fmaf(p.c, q.b, p.d * q.d);
    return r;
}

__global__ __launch_bounds__(BLOCK)
void bandpass_kernel(const float* __restrict__ x,
                     const float* __restrict__ p_cf,
                     const float* __restrict__ p_bw,
                     const float* __restrict__ p_gain,
                     const int*   __restrict__ p_sr,
                     float* __restrict__ out,
                     int T, int blocks_per_row)
{
    extern __shared__ float smem[];
    float*  __restrict__ s_in = smem;                          // IN_WORDS
    float2* __restrict__ scF  = (float2*)(smem + IN_WORDS);    // [0..3]=warp agg, [4]=s_blk

    const int tid  = threadIdx.x;
    const int lane = tid & 31;
    const int warp = tid >> 5;
    const int row  = blockIdx.x / blocks_per_row;
    const int sblk = blockIdx.x - row * blocks_per_row;
    const int S0   = sblk * SPAN;

    const float* __restrict__ xr   = x   + (size_t)row * T;
    float* __restrict__       orow = out + (size_t)row * T;

    // ---- biquad coefficients (HP1 x LP1 product, scipy butter(1,.) bilinear) ----
    const float cf   = *p_cf;
    const float bw   = *p_bw;
    const float gain = *p_gain;
    const float nyq  = 0.5f * (float)(*p_sr);
    const float PI_  = 3.14159265358979323846f;

    const float Kh  = tanf(PI_ * ((cf - 0.5f * bw) / nyq) * 0.5f);
    const float ah1 = (Kh - 1.0f) / (Kh + 1.0f);
    const float bh0 = 1.0f / (Kh + 1.0f);
    const float Kl  = tanf(PI_ * ((cf + 0.5f * bw) / nyq) * 0.5f);
    const float al1 = (Kl - 1.0f) / (Kl + 1.0f);
    const float bl0 = Kl / (Kl + 1.0f);

    const float na1 = -(ah1 + al1);   // y = na1*y1 + na2*y2 + gg*(x - x2)
    const float na2 = -(ah1 * al1);
    const float gg  = bh0 * bl0 * gain;

    // ---- fill: coalesced load of [S0-PRE, S0+SPAN), zeros before row start ----
    {
        const int total4 = IN_WORDS / 4;                       // 1089
        #pragma unroll
        for (int m = 0; m < (IN_WORDS / 4 + BLOCK - 1) / BLOCK; m++) {
            const int idx = m * BLOCK + tid;
            if (idx < total4) {
                const int e = S0 - PRE + 4 * idx;
                float4 v;
                if (e >= 0) v = *reinterpret_cast<const float4*>(xr + e);
                else        v = make_float4(0.f, 0.f, 0.f, 0.f);
                *reinterpret_cast<float4*>(s_in + SW(4 * idx)) = v;
            }
        }
    }
    __syncthreads();

    // one zero-y-state filter step (exact x history)
    #define P1_STEP(XC, PJ)                           \
        {                                             \
            float u_  = gg * ((XC) - x_2);            \
            float t0_ = fmaf(na2, y_2, u_);           \
            float yn_ = fmaf(na1, y_1, t0_);          \
            x_2 = x_1; x_1 = (XC);                    \
            y_2 = y_1; y_1 = yn_;                     \
            (PJ) = yn_;                               \
        }

    // ---- pass 1: particular solution of own chunk, zero incoming y-state ----
    float p[CH];
    float2 f;
    {
        const int base = PRE + tid * CH;
        float x_1 = s_in[SW(base - 1)];
        float x_2 = s_in[SW(base - 2)];
        float y_1 = 0.0f, y_2 = 0.0f;
        #pragma unroll
        for (int j = 0; j < CH; j += 4) {
            float4 v = *reinterpret_cast<const float4*>(s_in + SW(base + j));
            P1_STEP(v.x, p[j + 0]); P1_STEP(v.y, p[j + 1]);
            P1_STEP(v.z, p[j + 2]); P1_STEP(v.w, p[j + 3]);
        }
        f.x = y_1; f.y = y_2;
    }

    // ---- A^32 (5 squarings), uniform across threads ----
    M2 A32; { M2 A; A.a = na1; A.b = na2; A.c = 1.0f; A.d = 0.0f;
              A32 = msq(A); A32 = msq(A32); A32 = msq(A32);
              A32 = msq(A32); A32 = msq(A32); }

    // ---- history: warp 0 filters 8 chunks covering [S0-256, S0) ----
    if (tid < 32) {
        const int k    = lane & (NHIST - 1);
        const int base = 4 + k * CH;
        float x_1 = s_in[SW(base - 1)];
        float x_2 = s_in[SW(base - 2)];
        float y_1 = 0.0f, y_2 = 0.0f;
        float dummy;
        #pragma unroll
        for (int j = 0; j < CH; j += 4) {
            float4 v = *reinterpret_cast<const float4*>(s_in + SW(base + j));
            P1_STEP(v.x, dummy); P1_STEP(v.y, dummy);
            P1_STEP(v.z, dummy); P1_STEP(v.w, dummy);
        }
        (void)dummy;
        float2 fh = make_float2(y_1, y_2);
        float2 s  = make_float2(0.f, 0.f);           // zero state 256 back (~1e-11)
        #pragma unroll
        for (int q = 0; q < NHIST; q++) {            // compose in time order
            float fx = __shfl_sync(0xffffffffu, fh.x, q);
            float fy = __shfl_sync(0xffffffffu, fh.y, q);
            float sx = fmaf(A32.a, s.x, fmaf(A32.b, s.y, fx));
            float sy = fmaf(A32.c, s.x, fmaf(A32.d, s.y, fy));
            s.x = sx; s.y = sy;
        }
        if (lane == 0) scF[4] = s;                   // block incoming state
    }

    // ---- within-warp inclusive affine scan + per-thread V = A^(32*lane) ----
    float2 P = f;
    M2 L = A32;                                      // level matrix A^(32*2^k)
    M2 V; V.a = 1.0f; V.b = 0.0f; V.c = 0.0f; V.d = 1.0f;
    #pragma unroll
    for (int k = 0; k < 5; k++) {
        const int d = 1 << k;
        float px = __shfl_up_sync(0xffffffffu, P.x, d);
        float py = __shfl_up_sync(0xffffffffu, P.y, d);
        if (lane >= d) {                             // suffix length == d here
            P.x = fmaf(L.a, px, fmaf(L.b, py, P.x));
            P.y = fmaf(L.c, px, fmaf(L.d, py, P.y));
        }
        if ((lane >> k) & 1) V = mmul(L, V);         // build A^(32*lane)
        L = msq(L);
    }
    // L = A^1024 now. Publish warp aggregates.
    if (lane == 31) scF[warp] = P;
    __syncthreads();

    // ---- incoming state of my warp's 1024-sample segment ----
    float2 W = scF[4];                               // = s_blk
    #pragma unroll
    for (int w2 = 0; w2 < 3; w2++) {
        if (w2 < warp) {
            float2 Fw = scF[w2];
            float wx = fmaf(L.a, W.x, fmaf(L.b, W.y, Fw.x));
            float wy = fmaf(L.c, W.x, fmaf(L.d, W.y, Fw.y));
            W.x = wx; W.y = wy;
        }
    }

    // ---- exact incoming state of my chunk: delta = V*W + Q (exclusive offset) ----
    float Qx = __shfl_up_sync(0xffffffffu, P.x, 1);
    float Qy = __shfl_up_sync(0xffffffffu, P.y, 1);
    if (lane == 0) { Qx = 0.0f; Qy = 0.0f; }
    float2 delta;
    delta.x = fmaf(V.a, W.x, fmaf(V.b, W.y, Qx));
    delta.y = fmaf(V.c, W.x, fmaf(V.d, W.y, Qy));

    // ---- pass 2: homogeneous correction + write into reused s_in ----
    {
        float h1 = delta.x, h2 = delta.y;
        const int ob = tid * CH;
        #pragma unroll
        for (int j = 0; j < CH; j += 4) {
            float4 o;
            float hA = fmaf(na1, h1, na2 * h2);
            float hB = fmaf(na1, hA, na2 * h1);
            float hC = fmaf(na1, hB, na2 * hA);
            float hD = fmaf(na1, hC, na2 * hB);
            o.x = p[j + 0] + hA; o.y = p[j + 1] + hB;
            o.z = p[j + 2] + hC; o.w = p[j + 3] + hD;
            h2 = hC; h1 = hD;
            *reinterpret_cast<float4*>(s_in + SW(ob + j)) = o;
        }
    }
    __syncthreads();

    // ---- drain: coalesced smem -> gmem ----
    #pragma unroll
    for (int m = 0; m < SPAN / 4 / BLOCK; m++) {
        const int w = 4 * (m * BLOCK + tid);
        float4 v = *reinterpret_cast<const float4*>(s_in + SW(w));
        *reinterpret_cast<float4*>(orow + S0 + w) = v;
    }
    #undef P1_STEP
}

extern "C" void kernel_launch(void* const* d_in, const int* in_sizes, int n_in,
                              void* d_out, int out_size)
{
    const float* x    = (const float*)d_in[0];
    const float* cf   = (const float*)d_in[1];
    const float* bw   = (const float*)d_in[2];
    const float* gain = (const float*)d_in[3];
    const int*   sr   = (const int*)  d_in[4];
    float*       out  = (float*)d_out;

    const int B = 128;
    const int T = in_sizes[0] / B;                 // 262144
    const int blocks_per_row = T / SPAN;           // 64
    const int grid = B * blocks_per_row;           // 8192

    cudaFuncSetAttribute(bandpass_kernel,
                         cudaFuncAttributeMaxDynamicSharedMemorySize, SMEM_BYTES);
    bandpass_kernel<<<grid, BLOCK, SMEM_BYTES>>>(x, cf, bw, gain, sr, out,
                                                 T, blocks_per_row);
}